// round 11
// baseline (speedup 1.0000x reference)
#include <cuda_runtime.h>
#include <math.h>

#define BB 32
#define HWT 12544          // 112*112
#define CC 256
#define HID 32
#define CHUNKS 32          // pool CTAs per batch
#define ROWS_PER_CHUNK (HWT / CHUNKS)     // 392
#define RG 4
#define ROWS_PER_RG (ROWS_PER_CHUNK / RG) // 98
#define NPART (CHUNKS * RG)               // 128 partials per (b,c)
#define F4_PER_ROW (CC / 4)               // 64
#define F4_PER_B ((size_t)HWT * F4_PER_ROW)   // 802816
#define BLOCKS3 98
#define F4_PER_BLOCK3 (F4_PER_B / BLOCKS3)    // 8192
#define PF 8               // prefetched float4s per thread in scale prologue

__device__ float g_psum[BB][NPART][CC];
__device__ float g_pmax[BB][NPART][CC];
__device__ float g_scale[BB][CC];
__device__ int   g_cnt[BB];               // zero at load; self-resetting

// Kernel 1: partial pooling + last-arrival fan-in MLP tail.
// Calls the PDL trigger right after partials are stored, so the scale
// kernel's first wave can ramp up while the fan-in/MLP tail runs.
__global__ void __launch_bounds__(256) pool_mlp_kernel(
    const float* __restrict__ x,
    const float* __restrict__ w1, const float* __restrict__ b1,
    const float* __restrict__ w2, const float* __restrict__ b2)
{
    const int b = blockIdx.y;
    const int chunk = blockIdx.x;
    const int tid = threadIdx.x;
    const int c4 = tid & 63;
    const int rg = tid >> 6;

    const size_t row0 = (size_t)b * HWT + (size_t)chunk * ROWS_PER_CHUNK + (size_t)rg * ROWS_PER_RG;
    const float4* __restrict__ xp = reinterpret_cast<const float4*>(x) + row0 * F4_PER_ROW + c4;

    float4 s = make_float4(0.f, 0.f, 0.f, 0.f);
    float4 m = make_float4(-INFINITY, -INFINITY, -INFINITY, -INFINITY);
    #pragma unroll 7
    for (int r = 0; r < ROWS_PER_RG; ++r) {
        float4 v = __ldcg(xp + (size_t)r * F4_PER_ROW);
        s.x += v.x; s.y += v.y; s.z += v.z; s.w += v.w;
        m.x = fmaxf(m.x, v.x); m.y = fmaxf(m.y, v.y);
        m.z = fmaxf(m.z, v.z); m.w = fmaxf(m.w, v.w);
    }
    const int p = chunk * RG + rg;
    reinterpret_cast<float4*>(&g_psum[b][p][0])[c4] = s;
    reinterpret_cast<float4*>(&g_pmax[b][p][0])[c4] = m;

    // PDL: my streaming work is done — let the scale kernel start ramping.
    cudaTriggerProgrammaticLaunchCompletion();

    // ---- last-CTA-arrival fan-in: reduce 128 partials + MLP + sigmoid ----
    __shared__ int s_last;
    __threadfence();                       // release my partials
    __syncthreads();
    if (tid == 0) {
        int old = atomicAdd(&g_cnt[b], 1);
        s_last = (old == CHUNKS - 1);
        if (s_last) {
            g_cnt[b] = 0;                  // self-reset for graph replays
            __threadfence();               // acquire all partials
        }
    }
    __syncthreads();
    if (!s_last) return;

    __shared__ float s_avg[CC];
    __shared__ float s_max[CC];
    __shared__ float s_h[2 * HID];

    float sum = 0.f, mx = -INFINITY;
    #pragma unroll 16
    for (int q = 0; q < NPART; ++q) {
        sum += __ldcg(&g_psum[b][q][tid]);
        mx = fmaxf(mx, __ldcg(&g_pmax[b][q][tid]));
    }
    s_avg[tid] = sum * (1.0f / (float)HWT);
    s_max[tid] = mx;
    __syncthreads();

    {   // hidden layer: 64 outputs (avg 0..31, max 32..63), 4 threads/output
        int oi = tid >> 2;
        int part = tid & 3;
        int j = oi & (HID - 1);
        const float* pool = (oi < HID) ? s_avg : s_max;
        float acc = 0.f;
        #pragma unroll 16
        for (int i = part * 64; i < part * 64 + 64; ++i)
            acc += pool[i] * w1[i * HID + j];
        acc += __shfl_down_sync(0xffffffffu, acc, 1);
        acc += __shfl_down_sync(0xffffffffu, acc, 2);
        if (part == 0) s_h[oi] = fmaxf(acc + b1[j], 0.f);
    }
    __syncthreads();

    {   // output layer: 2*b2 + (hA+hM) @ w2, sigmoid
        float acc = 2.0f * b2[tid];
        #pragma unroll
        for (int j = 0; j < HID; ++j)
            acc += (s_h[j] + s_h[HID + j]) * w2[j * CC + tid];
        g_scale[b][tid] = 1.0f / (1.0f + expf(-acc));
    }
}

// Kernel 2: out = x * scale. grid (BLOCKS3, BB), 256 thr.
// PDL secondary: prefetch PF float4s of x (independent of pool) into regs,
// then grid-dependency-sync, then load scale and stream the rest.
// Descending batch order: first wave touches the batches pool read last
// (still L2-resident), so both prefetch and early main-loop reads hit L2.
__global__ void __launch_bounds__(256) scale_kernel(const float* __restrict__ x,
                                                    float* __restrict__ out) {
    const int b = (BB - 1) - blockIdx.y;   // descending
    const int tid = threadIdx.x;

    const size_t base = (size_t)b * F4_PER_B + (size_t)blockIdx.x * F4_PER_BLOCK3;
    const float4* __restrict__ xi = reinterpret_cast<const float4*>(x) + base;
    float4* __restrict__ xo = reinterpret_cast<float4*>(out) + base;

    // Prologue (runs before the pool grid fully completes): prefetch x.
    float4 pre[PF];
    #pragma unroll
    for (int j = 0; j < PF; ++j)
        pre[j] = __ldcs(xi + tid + j * 256);

    // Wait for the pool kernel (and its MLP tail) to finish entirely.
    cudaGridDependencySynchronize();

    const float4 sc = reinterpret_cast<const float4*>(&g_scale[b][0])[tid & 63];

    #pragma unroll
    for (int j = 0; j < PF; ++j) {
        float4 v = pre[j];
        v.x *= sc.x; v.y *= sc.y; v.z *= sc.z; v.w *= sc.w;
        __stcs(xo + tid + j * 256, v);
    }
    #pragma unroll 8
    for (int i = tid + PF * 256; i < F4_PER_BLOCK3; i += 256) {
        float4 v = __ldcs(xi + i);                 // last use: evict-first
        v.x *= sc.x; v.y *= sc.y; v.z *= sc.z; v.w *= sc.w;
        __stcs(xo + i, v);                         // streaming store
    }
}

extern "C" void kernel_launch(void* const* d_in, const int* in_sizes, int n_in,
                              void* d_out, int out_size) {
    const float* x  = (const float*)d_in[0];
    const float* w1 = (const float*)d_in[1];
    const float* b1 = (const float*)d_in[2];
    const float* w2 = (const float*)d_in[3];
    const float* b2 = (const float*)d_in[4];
    float* out = (float*)d_out;

    pool_mlp_kernel<<<dim3(CHUNKS, BB), 256>>>(x, w1, b1, w2, b2);

    // Secondary launch with programmatic dependency (PDL).
    cudaLaunchAttribute attr[1];
    attr[0].id = cudaLaunchAttributeProgrammaticStreamSerialization;
    attr[0].val.programmaticStreamSerializationAllowed = 1;
    cudaLaunchConfig_t cfg = {};
    cfg.gridDim = dim3(BLOCKS3, BB);
    cfg.blockDim = dim3(256, 1, 1);
    cfg.dynamicSmemBytes = 0;
    cfg.stream = 0;
    cfg.attrs = attr;
    cfg.numAttrs = 1;
    cudaLaunchKernelEx(&cfg, scale_kernel, x, out);
}

// round 12
// speedup vs baseline: 1.0374x; 1.0374x over previous
#include <cuda_runtime.h>
#include <math.h>

#define BB 32
#define HWT 12544          // 112*112
#define CC 256
#define HID 32
#define CHUNKS 32
#define ROWS_PER_CHUNK (HWT / CHUNKS)     // 392
#define RG 4
#define ROWS_PER_RG (ROWS_PER_CHUNK / RG) // 98
#define NPART (CHUNKS * RG)               // 128 partials per (b,c)
#define F4_PER_ROW (CC / 4)               // 64
#define F4_PER_B ((size_t)HWT * F4_PER_ROW)   // 802816
#define BLOCKS3 98
#define F4_PER_BLOCK3 (F4_PER_B / BLOCKS3)    // 8192

__device__ float g_psum[BB][NPART][CC];
__device__ float g_pmax[BB][NPART][CC];
__device__ float g_scale[BB][CC];

// Kernel 1: partial sum/max pooling. grid (CHUNKS, B), 256 threads.
// Thread = (rg, c4): one float4 channel group, 98 rows. Pure streaming,
// no atomics/fences (R1-validated at 6.48 TB/s, 64.1us).
__global__ void __launch_bounds__(256) pool_kernel(const float* __restrict__ x) {
    const int b = blockIdx.y;
    const int chunk = blockIdx.x;
    const int tid = threadIdx.x;
    const int c4 = tid & 63;
    const int rg = tid >> 6;

    const size_t row0 = (size_t)b * HWT + (size_t)chunk * ROWS_PER_CHUNK + (size_t)rg * ROWS_PER_RG;
    const float4* __restrict__ xp = reinterpret_cast<const float4*>(x) + row0 * F4_PER_ROW + c4;

    float4 s = make_float4(0.f, 0.f, 0.f, 0.f);
    float4 m = make_float4(-INFINITY, -INFINITY, -INFINITY, -INFINITY);
    #pragma unroll 7
    for (int r = 0; r < ROWS_PER_RG; ++r) {
        float4 v = xp[(size_t)r * F4_PER_ROW];
        s.x += v.x; s.y += v.y; s.z += v.z; s.w += v.w;
        m.x = fmaxf(m.x, v.x); m.y = fmaxf(m.y, v.y);
        m.z = fmaxf(m.z, v.z); m.w = fmaxf(m.w, v.w);
    }
    const int p = chunk * RG + rg;
    reinterpret_cast<float4*>(&g_psum[b][p][0])[c4] = s;
    reinterpret_cast<float4*>(&g_pmax[b][p][0])[c4] = m;
}

// Kernel 2: final reduction + dual-branch MLP + sigmoid. grid (B), 256 thr.
__global__ void __launch_bounds__(256) mlp_kernel(const float* __restrict__ w1,
                                                  const float* __restrict__ b1,
                                                  const float* __restrict__ w2,
                                                  const float* __restrict__ b2) {
    const int b = blockIdx.x;
    const int c = threadIdx.x;

    float s = 0.f;
    float m = -INFINITY;
    #pragma unroll 16
    for (int p = 0; p < NPART; ++p) {
        s += g_psum[b][p][c];
        m = fmaxf(m, g_pmax[b][p][c]);
    }

    __shared__ float s_avg[CC];
    __shared__ float s_max[CC];
    __shared__ float s_h[2 * HID];
    s_avg[c] = s * (1.0f / (float)HWT);
    s_max[c] = m;
    __syncthreads();

    {   // hidden layer: 64 outputs (avg 0..31, max 32..63), 4 threads/output
        int oi = c >> 2;
        int part = c & 3;
        int j = oi & (HID - 1);
        const float* pool = (oi < HID) ? s_avg : s_max;
        float acc = 0.f;
        #pragma unroll 16
        for (int i = part * 64; i < part * 64 + 64; ++i)
            acc += pool[i] * w1[i * HID + j];
        acc += __shfl_down_sync(0xffffffffu, acc, 1);
        acc += __shfl_down_sync(0xffffffffu, acc, 2);
        if (part == 0) s_h[oi] = fmaxf(acc + b1[j], 0.f);
    }
    __syncthreads();

    {   // output layer: out = 2*b2 + (hA+hM) @ w2, then sigmoid
        float acc = 2.0f * b2[c];
        #pragma unroll
        for (int j = 0; j < HID; ++j)
            acc += (s_h[j] + s_h[HID + j]) * w2[j * CC + c];
        g_scale[b][c] = 1.0f / (1.0f + expf(-acc));
    }
}

// Kernel 3: out = x * scale. grid (BLOCKS3, BB), 256 thr.
// DESCENDING batch order: first wave touches the batches the pool kernel
// read last (still L2-resident) -> ~120MB of reads become L2 hits
// (R10-validated: 143us -> 124us).
__global__ void __launch_bounds__(256) scale_kernel(const float* __restrict__ x,
                                                    float* __restrict__ out) {
    const int b = (BB - 1) - blockIdx.y;   // descending
    const int tid = threadIdx.x;
    const float4 sc = reinterpret_cast<const float4*>(&g_scale[b][0])[tid & 63];

    const size_t base = (size_t)b * F4_PER_B + (size_t)blockIdx.x * F4_PER_BLOCK3;
    const float4* __restrict__ xi = reinterpret_cast<const float4*>(x) + base;
    float4* __restrict__ xo = reinterpret_cast<float4*>(out) + base;

    #pragma unroll 8
    for (int i = tid; i < F4_PER_BLOCK3; i += 256) {
        float4 v = __ldcs(xi + i);                 // last use: evict-first
        v.x *= sc.x; v.y *= sc.y; v.z *= sc.z; v.w *= sc.w;
        __stcs(xo + i, v);                         // streaming store
    }
}

extern "C" void kernel_launch(void* const* d_in, const int* in_sizes, int n_in,
                              void* d_out, int out_size) {
    const float* x  = (const float*)d_in[0];
    const float* w1 = (const float*)d_in[1];
    const float* b1 = (const float*)d_in[2];
    const float* w2 = (const float*)d_in[3];
    const float* b2 = (const float*)d_in[4];
    float* out = (float*)d_out;

    pool_kernel<<<dim3(CHUNKS, BB), 256>>>(x);
    mlp_kernel<<<BB, 256>>>(w1, b1, w2, b2);
    scale_kernel<<<dim3(BLOCKS3, BB), 256>>>(x, out);
}